// round 12
// baseline (speedup 1.0000x reference)
#include <cuda_runtime.h>
#include <math.h>

#define TPB 256
typedef unsigned long long ull;

// ---------------- shared-memory layout (floats) ----------------
// wfp   @0      [1200]  reflect-padded waveform (later part[1040])
// cwI   @1200   [2400]  interleaved (cumsum, wf) pairs + reflect halos
// dsp   @3600   [1200]  reflect-padded smoothed deriv
// buf   @4800   [1024]  d1-prefix / softplus out
// fnI   @5824   [2048]  interleaved (f1c0,f1c1) raw pairs + halos (1024 pairs)
// fn2   @7872   [1024]  f1c2 raw + halos
// f2b   @8896   [4860]  boundary f2 (normalized), 15 ch x stride 324
// cwp   @13756  [1560]  W-folded comb weights 15 x 104
// wsubI @15316  [1080]  per m: 24 interleaved (c0,c1) pairs [48] + c2 [24]
// wdvP  @16396  [124]
// wI    @16520  [248]   interleaved (wcaE, wx) taps
// kI    @16768  [248]   interleaved (keff0*invS0, keff1*invS1) taps
// k2    @17016  [124]   keff2*invS2
// red   @17140  [32]
// scal  @17172  [16]
#define SMEM_FLOATS 17188
#define F2B_STRIDE 324

__device__ __align__(16) float g_K3[1116];
__device__ __align__(16) float g_wcaEff[124];
__device__ float g_speMax;

// ================= precompute kernel (once per launch) =================
__global__ void Spot_pre_kernel(const float* __restrict__ spe,
                                const float* __restrict__ wca,
                                const float* __restrict__ wrl,
                                const float* __restrict__ wsub,
                                const float* __restrict__ wcomb){
  __shared__ float red[32];
  __shared__ float sh[2];
  int tid=threadIdx.x, lane=tid&31, wid=tid>>5;

  float m=-1e30f;
  for(int i=tid;i<1000;i+=TPB) m=fmaxf(m,spe[i]);
#pragma unroll
  for(int o=16;o>0;o>>=1) m=fmaxf(m,__shfl_xor_sync(0xffffffffu,m,o));
  if(lane==0) red[wid]=m;
  __syncthreads();
  if(tid==0){ float mm=red[0]; for(int i=1;i<TPB/32;i++) mm=fmaxf(mm,red[i]);
              sh[0]=mm; g_speMax=mm; }
  __syncthreads();

  float s=0.f;
  for(int i=tid;i<121;i+=TPB) s+=wca[i];
#pragma unroll
  for(int o=16;o>0;o>>=1) s+=__shfl_xor_sync(0xffffffffu,s,o);
  if(lane==0) red[wid]=s;
  __syncthreads();
  if(tid==0){ float ss=0; for(int i=0;i<TPB/32;i++) ss+=red[i]; sh[1]=ss; }
  __syncthreads();
  float swca=sh[1];

  for(int i=tid;i<124;i+=TPB){
    float a =(i<121)? wca[i]:0.f;
    float rl=(i<101)? wrl[i]:0.f;
    g_wcaEff[i]=a - swca*rl;
  }

  // K3[r][c][q] = sum_d sum_k wsub[3d+r][c][k] * wcomb[d][q-k][r]
  for(int e=tid;e<1116;e+=TPB){
    int r=e/372, rem=e-r*372, c=rem/124, q=rem-c*124;
    float acc=0.f;
    if(q<121){
      int klo=(q>100)? (q-100):0;
      int khi=(q<20)? q:20;
      float ad[5]={0,0,0,0,0};
      for(int d=0;d<5;d++){
        const float* ws = wsub + ((3*d+r)*3+c)*21;
        float a2=0.f;
        for(int k=klo;k<=khi;k++)
          a2 = fmaf(ws[k], wcomb[(d*101+(q-k))*3+r], a2);
        ad[d]=a2;
      }
      acc=((ad[0]+ad[1])+(ad[2]+ad[3]))+ad[4];
    }
    g_K3[e]=acc;
  }
}

// ================= packed-math helpers =================
__device__ __forceinline__ ull ffma2(ull a, ull b, ull c){
  ull d;
  asm("fma.rn.f32x2 %0, %1, %2, %3;" : "=l"(d) : "l"(a), "l"(b), "l"(c));
  return d;
}
__device__ __forceinline__ float2 unp(ull a){
  float x,y;
  asm("mov.b64 {%0, %1}, %2;" : "=f"(x), "=f"(y) : "l"(a));
  return make_float2(x,y);
}

// dual-channel conv: 4 outputs x 2 channels. src = interleaved pair array
// (float2 per position), base must point at an EVEN pair position (16B).
// w = interleaved taps. Exact float2 version of the scalar sliding window.
__device__ __forceinline__ void conv4d(const float* __restrict__ src,
                                       const float* __restrict__ w,
                                       int ng, ull* __restrict__ acc){
  const ulonglong2* S = reinterpret_cast<const ulonglong2*>(src);
  const ulonglong2* W = reinterpret_cast<const ulonglong2*>(w);
  ulonglong2 A = S[0];   // pairs p0,p1
  ulonglong2 B = S[1];   // pairs p2,p3
#pragma unroll 2
  for(int g=0; g<ng; g++){
    ulonglong2 C = S[2*g+2];   // p4,p5
    ulonglong2 D = S[2*g+3];   // p6,p7
    ulonglong2 W0 = W[2*g];    // taps 0,1
    ulonglong2 W1 = W[2*g+1];  // taps 2,3
    acc[0]=ffma2(W0.x,A.x,acc[0]); acc[1]=ffma2(W0.x,A.y,acc[1]);
    acc[2]=ffma2(W0.x,B.x,acc[2]); acc[3]=ffma2(W0.x,B.y,acc[3]);
    acc[0]=ffma2(W0.y,A.y,acc[0]); acc[1]=ffma2(W0.y,B.x,acc[1]);
    acc[2]=ffma2(W0.y,B.y,acc[2]); acc[3]=ffma2(W0.y,C.x,acc[3]);
    acc[0]=ffma2(W1.x,B.x,acc[0]); acc[1]=ffma2(W1.x,B.y,acc[1]);
    acc[2]=ffma2(W1.x,C.x,acc[2]); acc[3]=ffma2(W1.x,C.y,acc[3]);
    acc[0]=ffma2(W1.y,B.y,acc[0]); acc[1]=ffma2(W1.y,C.x,acc[1]);
    acc[2]=ffma2(W1.y,C.y,acc[2]); acc[3]=ffma2(W1.y,D.x,acc[3]);
    A=C; B=D;
  }
}

// scalar 4-output sliding-window conv
#define CONV4_BODY(x0,x1,wv,acc)                                               \
  acc[0]=fmaf(wv.x,x0.x,acc[0]); acc[1]=fmaf(wv.x,x0.y,acc[1]);                \
  acc[2]=fmaf(wv.x,x0.z,acc[2]); acc[3]=fmaf(wv.x,x0.w,acc[3]);                \
  acc[0]=fmaf(wv.y,x0.y,acc[0]); acc[1]=fmaf(wv.y,x0.z,acc[1]);                \
  acc[2]=fmaf(wv.y,x0.w,acc[2]); acc[3]=fmaf(wv.y,x1.x,acc[3]);                \
  acc[0]=fmaf(wv.z,x0.z,acc[0]); acc[1]=fmaf(wv.z,x0.w,acc[1]);                \
  acc[2]=fmaf(wv.z,x1.x,acc[2]); acc[3]=fmaf(wv.z,x1.y,acc[3]);                \
  acc[0]=fmaf(wv.w,x0.w,acc[0]); acc[1]=fmaf(wv.w,x1.x,acc[1]);                \
  acc[2]=fmaf(wv.w,x1.y,acc[2]); acc[3]=fmaf(wv.w,x1.z,acc[3]);

template<int NG>
__device__ __forceinline__ void conv4(const float* __restrict__ src,
                                      const float* __restrict__ w,
                                      float* __restrict__ acc){
  float4 x0 = *reinterpret_cast<const float4*>(src);
#pragma unroll
  for(int g=0; g<NG; g++){
    float4 x1 = *reinterpret_cast<const float4*>(src + 4*g + 4);
    float4 wv = *reinterpret_cast<const float4*>(w + 4*g);
    CONV4_BODY(x0,x1,wv,acc)
    x0=x1;
  }
}
__device__ __forceinline__ void conv4r(const float* __restrict__ src,
                                       const float* __restrict__ w,
                                       int ng, float* __restrict__ acc){
  float4 x0 = *reinterpret_cast<const float4*>(src);
#pragma unroll 2
  for(int g=0; g<ng; g++){
    float4 x1 = *reinterpret_cast<const float4*>(src + 4*g + 4);
    float4 wv = *reinterpret_cast<const float4*>(w + 4*g);
    CONV4_BODY(x0,x1,wv,acc)
    x0=x1;
  }
}

// ================= reduction helpers =================
__device__ __forceinline__ float warpRMax(float v){
#pragma unroll
  for(int o=16;o>0;o>>=1) v=fmaxf(v,__shfl_xor_sync(0xffffffffu,v,o));
  return v;
}
__device__ __forceinline__ float warpRSum(float v){
#pragma unroll
  for(int o=16;o>0;o>>=1) v+=__shfl_xor_sync(0xffffffffu,v,o);
  return v;
}
__device__ __forceinline__ void bredMax(float v, float* red, float* out){
  int lane=threadIdx.x&31, wid=threadIdx.x>>5;
  v=warpRMax(v);
  if(lane==0) red[wid]=v;
  __syncthreads();
  if(threadIdx.x==0){
    float m=red[0];
#pragma unroll
    for(int i=1;i<TPB/32;i++) m=fmaxf(m,red[i]);
    *out=m;
  }
  __syncthreads();
}
__device__ __forceinline__ void bredSum(float v, float* red, float* out){
  int lane=threadIdx.x&31, wid=threadIdx.x>>5;
  v=warpRSum(v);
  if(lane==0) red[wid]=v;
  __syncthreads();
  if(threadIdx.x==0){
    float s=red[0];
#pragma unroll
    for(int i=1;i<TPB/32;i++) s+=red[i];
    *out=s;
  }
  __syncthreads();
}

__device__ __forceinline__ float softplusf(float v){
  return (v>0.f) ? v + log1pf(__expf(-v)) : log1pf(__expf(v));
}

// boundary comb half-unit u in [0,260)
__device__ __forceinline__ void do_bnd(int u, const float* __restrict__ f2b,
                                       const float* __restrict__ cwp,
                                       float* __restrict__ part){
  int g26=u/10, q=u%10, p=q>>1, h=q&1;
  int side=g26/13, G=g26%13;
  const float* srcb = f2b + side*160 + 4*G + 52*h;
  const float* wb   = cwp + 52*h;
  float acc[4]={0,0,0,0};
  conv4r(srcb + (3*p  )*F2B_STRIDE, wb+(3*p  )*104, 13, acc);
  conv4r(srcb + (3*p+1)*F2B_STRIDE, wb+(3*p+1)*104, 13, acc);
  conv4r(srcb + (3*p+2)*F2B_STRIDE, wb+(3*p+2)*104, 13, acc);
  float* pp = part + u*4;
  pp[0]=acc[0]; pp[1]=acc[1]; pp[2]=acc[2]; pp[3]=acc[3];
}

// ================= main kernel =================
__global__ void __launch_bounds__(TPB,3) Spot_48610439856277_kernel(
  const float* __restrict__ g_wf, const float* __restrict__ g_mask,
  const float* __restrict__ g_wx, const float* __restrict__ g_wdv,
  const float* __restrict__ g_wsub, const float* __restrict__ g_wcomb,
  const float* __restrict__ g_wp,
  float* __restrict__ g_out)
{
  extern __shared__ float sm[];
  float* wfp  = sm;
  float* cwI  = sm + 1200;
  float* dsp  = sm + 3600;
  float* buf  = sm + 4800;
  float* fnI  = sm + 5824;
  float* fn2  = sm + 7872;
  float* f2b  = sm + 8896;
  float* cwp  = sm + 13756;
  float* wsubI= sm + 15316;
  float* wdvP = sm + 16396;
  float* wI   = sm + 16520;
  float* kI   = sm + 16768;
  float* k2   = sm + 17016;
  float* red  = sm + 17140;
  float* scal = sm + 17172;
  float* part = sm;   // overlays wfp after fit convs
  float2* cwI2=(float2*)cwI;
  float2* fnI2=(float2*)fnI;

  const int tid = threadIdx.x;
  const int lane = tid&31, wid = tid>>5;
  const int b   = blockIdx.x;
  const float* wf = g_wf  + (size_t)b*1000;
  const float* mk = g_mask+ (size_t)b*1000;
  float* outp     = g_out + (size_t)b*1000;

  // ---- preamble loads + pads ----
  for(int i=tid;i<1200;i+=TPB){
    int j=i-100; j = (j<0) ? -j : (j>999 ? 1998-j : j);
    wfp[i]=wf[j];
  }
  for(int i=tid;i<124;i+=TPB){
    float wcaV=g_wcaEff[i];
    float wxV =(i<121)? g_wx[i] :0.f;
    wI[2*i]=wcaV; wI[2*i+1]=wxV;
    wdvP[i]=(i<121)? g_wdv[i]:0.f;
  }
  for(int i=tid;i<1080;i+=TPB){
    int m=i/72, rem=i%72;
    float v;
    if(rem<48){ int k=rem>>1, cin=rem&1; v=(k<21)? g_wsub[(m*3+cin)*21+k]:0.f; }
    else      { int k=rem-48;            v=(k<21)? g_wsub[(m*3+2)*21+k]:0.f; }
    wsubI[i]=v;
  }
  // f2b zero pads: per channel [0,50), [150,160), [260,324)
  for(int i=tid;i<15*124;i+=TPB){
    int c=i/124, j=i%124;
    int off = (j<50)? j : (j<60? 150+(j-50) : 260+(j-60));
    f2b[c*F2B_STRIDE+off]=0.f;
  }
  if(tid<4){ fnI2[1020+tid]=make_float2(0.f,0.f); fn2[1020+tid]=0.f; }
  __syncthreads();

  // ================= Phase A: fused dual scan (cumsum + d1-prefix) + wf max
  {
    int t0=4*tid;
    float la0=0,la1=0,la2=0,la3=0;
    float ld0=0,ld1=0,ld2=0,ld3=0;
    float a0=0,a1=0,a2v=0,a3=0;
    float vmax=-1e30f;
    if(t0<1000){
      a0=wfp[100+t0]; a1=wfp[101+t0]; a2v=wfp[102+t0]; a3=wfp[103+t0];
      la0=a0; la1=la0+a1; la2=la1+a2v; la3=la2+a3;
      vmax=fmaxf(fmaxf(a0,a1),fmaxf(a2v,a3));
      const float dw0=1.f/280.f, dw1=-4.f/105.f, dw2=0.2f, dw3=-0.8f,
                  dw5=0.8f, dw6=-0.2f, dw7=4.f/105.f, dw8=-1.f/280.f;
#pragma unroll
      for(int j=0;j<4;j++){
        int t=t0+j;
        float s=0.f;
        if(t>=4)    s=fmaf(dw0, wfp[ 96+t], s);
        if(t>=3)    s=fmaf(dw1, wfp[ 97+t], s);
        if(t>=2)    s=fmaf(dw2, wfp[ 98+t], s);
        if(t>=1)    s=fmaf(dw3, wfp[ 99+t], s);
        if(t<=998)  s=fmaf(dw5, wfp[101+t], s);
        if(t<=997)  s=fmaf(dw6, wfp[102+t], s);
        if(t<=996)  s=fmaf(dw7, wfp[103+t], s);
        if(t<=995)  s=fmaf(dw8, wfp[104+t], s);
        if(j==0){ ld0=s; } else if(j==1){ ld1=ld0+s; }
        else if(j==2){ ld2=ld1+s; } else { ld3=ld2+s; }
      }
    }
    float csA=la3, xA=csA, csB=ld3, xB=csB;
#pragma unroll
    for(int o=1;o<32;o<<=1){
      float yA=__shfl_up_sync(0xffffffffu,xA,o); if(lane>=o) xA+=yA;
      float yB=__shfl_up_sync(0xffffffffu,xB,o); if(lane>=o) xB+=yB;
    }
    if(lane==31){ red[wid]=xA; red[8+wid]=xB; }
    float wm=warpRMax(vmax);
    if(lane==0) red[16+wid]=wm;
    __syncthreads();
    if(wid==0){
      float z=(lane<8)? red[lane]:0.f;
#pragma unroll
      for(int o=1;o<8;o<<=1){ float y=__shfl_up_sync(0xffffffffu,z,o); if(lane>=o) z+=y; }
      if(lane<8) red[lane]=z;
    } else if(wid==1){
      float z=(lane<8)? red[8+lane]:0.f;
#pragma unroll
      for(int o=1;o<8;o<<=1){ float y=__shfl_up_sync(0xffffffffu,z,o); if(lane>=o) z+=y; }
      if(lane<8) red[8+lane]=z;
    } else if(wid==2 && lane==0){
      float m=red[16];
#pragma unroll
      for(int i=17;i<24;i++) m=fmaxf(m,red[i]);
      scal[0]=m;
    }
    __syncthreads();
    float preA = xA - csA + ((wid>0)? red[wid-1]:0.f);
    float preB = xB - csB + ((wid>0)? red[8+wid-1]:0.f);
    if(t0<1000){
      cwI2[100+t0]=make_float2(preA+la0, a0);
      cwI2[101+t0]=make_float2(preA+la1, a1);
      cwI2[102+t0]=make_float2(preA+la2, a2v);
      cwI2[103+t0]=make_float2(preA+la3, a3);
      buf[t0  ]=preB+ld0; buf[t0+1]=preB+ld1;
      buf[t0+2]=preB+ld2; buf[t0+3]=preB+ld3;
    }
    if(tid==0){  // gate W
      float h = scal[0]/g_speMax;
      float e0=-fmaxf(h-g_wp[0],0.f);
      float e1=-fmaxf(h-g_wp[1],0.f);
      float e2=-fmaxf(h-g_wp[2],0.f);
      float mg=fmaxf(e0,fmaxf(e1,e2));
      float p0=__expf(e0-mg),p1=__expf(e1-mg),p2=__expf(e2-mg);
      float is=1.f/(p0+p1+p2);
      scal[3]=p0*is; scal[4]=p1*is; scal[5]=p2*is;
    }
  }
  __syncthreads();

  // ================= Phase B: cwI halos, dsp from prefixes, cwp build
  for(int i=tid;i<100;i+=TPB){ cwI2[i]=cwI2[200-i]; cwI2[1100+i]=cwI2[1098-i]; }
  for(int t=tid;t<1000;t+=TPB){
    int hi = (t+25>999)? 999 : t+25;
    float p = buf[hi] - ((t>=26)? buf[t-26] : 0.f);
    dsp[100+t]=p*(1.f/51.f);
  }
  for(int i=tid;i<100;i+=TPB){
    int tm=100-i;
    dsp[i] = (buf[tm+25] - ((tm>=26)? buf[tm-26]:0.f))*(1.f/51.f);
    int tr=998-i;
    int hi=(tr+25>999)? 999 : tr+25;
    dsp[1100+i] = (buf[hi] - buf[tr-26])*(1.f/51.f);
  }
  for(int i=tid;i<1560;i+=TPB){
    int c=i/104, hh=i%104, d=c/3, r=c%3;
    cwp[i] = (hh<101) ? scal[3+r]*g_wcomb[(d*101+hh)*3+r] : 0.f;
  }
  __syncthreads();

  // ================= Phase C: fit convs (dual c01 + scalar c2) + inline sums
  float ls0=0.f, ls1=0.f, ls2=0.f;
  if(tid<250){
    int t0=4*tid;
    ull ad[4]={0,0,0,0};
    conv4d(cwI + 2*t0, wI, 31, ad);
    float as[4]={0,0,0,0};
    conv4r(dsp + t0, wdvP, 31, as);
#pragma unroll
    for(int j=0;j<4;j++){
      float2 v=unp(ad[j]);
      float r0=fmaxf(v.x,0.f), r1=fmaxf(v.y,0.f), r2=fmaxf(as[j],0.f);
      fnI2[10+t0+j]=make_float2(r0,r1);
      fn2[10+t0+j]=r2;
      ls0+=r0; ls1+=r1; ls2+=r2;
    }
  }
  {
    float s0=warpRSum(ls0), s1=warpRSum(ls1), s2=warpRSum(ls2);
    if(lane==0){ red[wid]=s0; red[8+wid]=s1; red[16+wid]=s2; }
    __syncthreads();
    if(tid==0){
      float S0=0,S1=0,S2=0;
#pragma unroll
      for(int i=0;i<8;i++){ S0+=red[i]; S1+=red[8+i]; S2+=red[16+i]; }
      scal[6]=1.f/(S0+1e-10f); scal[7]=1.f/(S1+1e-10f); scal[8]=1.f/(S2+1e-10f);
    }
    __syncthreads();
  }

  // ================= Phase D: halos, kI/k2 build (W,invS folded), wsubI*=invS
  for(int i=tid;i<20;i+=TPB){
    if(i<10){ fnI2[i]=fnI2[20-i]; fn2[i]=fn2[20-i]; }
    else { int p=1010+(i-10); fnI2[p]=fnI2[2018-p]; fn2[p]=fn2[2018-p]; }
  }
  for(int i=tid;i<124;i+=TPB){
    float W0=scal[3], W1=scal[4], W2=scal[5];
    float k0=(W0*g_K3[i]     + W1*g_K3[372+i]     + W2*g_K3[744+i]    )*scal[6];
    float k1=(W0*g_K3[124+i] + W1*g_K3[372+124+i] + W2*g_K3[744+124+i])*scal[7];
    float kc2=(W0*g_K3[248+i]+ W1*g_K3[372+248+i] + W2*g_K3[744+248+i])*scal[8];
    ((float2*)kI)[i]=make_float2(k0,k1);
    k2[i]=kc2;
  }
  for(int i=tid;i<1080;i+=TPB){
    int rem=i%72;
    float s = (rem<48)? ((rem&1)? scal[7]:scal[6]) : scal[8];
    wsubI[i]*=s;
  }
  __syncthreads();

  // ================= Phase E: boundary f2 (dual cin01 + scalar cin2)
#pragma unroll 1
  for(int rr=0; rr<3; rr++){
    if(tid<250){
      int u=rr*250+tid;
      int m=u/50, g=u%50;
      int u0 = (g<25)? 4*g : (900+4*(g-25));
      int so = (g<25)? (50+4*g) : (160+4*(g-25));
      ull ad[4]={0,0,0,0};
      float as[4]={0,0,0,0};
      conv4d(fnI + 2*u0, wsubI + m*72, 6, ad);
      conv4<6>(fn2 + u0, wsubI + m*72 + 48, as);
      float* o = f2b + m*F2B_STRIDE + so;
#pragma unroll
      for(int j=0;j<4;j++){
        float2 v=unp(ad[j]);
        o[j]=(v.x+v.y)+as[j];
      }
    }
  }
  __syncthreads();

  // ================= Phase F: interior composite (dual) || boundary comb
  if(tid<225){
    int t0=50+4*tid;
    ull ad[4]={0,0,0,0};
    float as[4]={0,0,0,0};
    conv4d(fnI + 2*(4*tid), kI, 31, ad);
    conv4r(fn2 + 4*tid, k2, 31, as);
#pragma unroll
    for(int j=0;j<4;j++){
      float2 v=unp(ad[j]);
      buf[t0+j]=softplusf((v.x+v.y)+as[j]);
    }
  }
  // boundary: 260 half-units; tid>=225 take 2 each (u 0..61), tid<198 one each
  if(tid>=225){
    do_bnd(tid-225, f2b, cwp, part);
    do_bnd(tid-225+31, f2b, cwp, part);
  } else if(tid<198){
    do_bnd(62+tid, f2b, cwp, part);
  }
  __syncthreads();
  if(tid<104){
    int g26=tid/4, j=tid%4;
    int side=g26/13, G=g26%13;
    int t = side ? (950+4*G+j) : (4*G+j);
    bool valid = side ? (t<1000) : (t<50);
    if(valid){
      float v=0.f;
#pragma unroll
      for(int q=0;q<10;q++) v+=part[(g26*10+q)*4+j];
      buf[t]=softplusf(v);
    }
  }
  __syncthreads();

  // ================= epilogue: amax, masked scale, 1e4-softmax
  {
    float om=-1e30f;
    for(int t=tid;t<1000;t+=TPB) om=fmaxf(om,buf[t]);
    bredMax(om,red,&scal[9]);
    float amax = scal[9] + 1e-10f;

    float ym=-1e30f;
    for(int t=tid;t<1000;t+=TPB){
      float y = 1e4f * ((buf[t]/amax)*mk[t]);
      buf[t]=y; ym=fmaxf(ym,y);
    }
    bredMax(ym,red,&scal[10]);
    float ymax=scal[10];

    float ssum=0.f;
    for(int t=tid;t<1000;t+=TPB){
      float p=__expf(buf[t]-ymax);
      buf[t]=p; ssum+=p;
    }
    bredSum(ssum,red,&scal[11]);
    float isum=1.f/scal[11];
    for(int t=tid;t<1000;t+=TPB) outp[t]=buf[t]*isum;
  }
}

extern "C" void kernel_launch(void* const* d_in, const int* in_sizes, int n_in,
                              void* d_out, int out_size) {
  const float* wf    = (const float*)d_in[0];
  const float* mask  = (const float*)d_in[1];
  const float* SPE   = (const float*)d_in[2];
  const float* wca   = (const float*)d_in[3];
  const float* wx    = (const float*)d_in[4];
  const float* wdv   = (const float*)d_in[5];
  const float* wrl   = (const float*)d_in[6];
  const float* wsub  = (const float*)d_in[7];
  const float* wcomb = (const float*)d_in[8];
  const float* wp    = (const float*)d_in[9];
  float* out = (float*)d_out;

  int B = in_sizes[0] / 1000;
  size_t smem = SMEM_FLOATS * sizeof(float);
  cudaFuncSetAttribute(Spot_48610439856277_kernel,
                       cudaFuncAttributeMaxDynamicSharedMemorySize, (int)smem);

  Spot_pre_kernel<<<1, TPB>>>(SPE, wca, wrl, wsub, wcomb);
  Spot_48610439856277_kernel<<<B, TPB, smem>>>(wf, mask, wx, wdv,
                                               wsub, wcomb, wp, out);
}

// round 13
// speedup vs baseline: 1.0030x; 1.0030x over previous
#include <cuda_runtime.h>
#include <math.h>

#define TPB 256
typedef unsigned long long ull;

// ---------------- shared-memory layout (floats) ----------------
// wfp   @0      [1200]  reflect-padded waveform (later part[1040])
// cwI   @1200   [2400]  interleaved (cumsum, wf) pairs + reflect halos
// dsp   @3600   [1200]  reflect-padded smoothed deriv
// buf   @4800   [1024]  d1-prefix / softplus out
// fnI   @5824   [2048]  interleaved (f1c0,f1c1) raw pairs + halos (1024 pairs)
// fn2   @7872   [1024]  f1c2 raw + halos
// f2b   @8896   [4860]  boundary f2 (normalized), 15 ch x stride 324
// cwp   @13756  [1560]  W-folded comb weights 15 x 104
// wsubI @15316  [1080]  per m: 24 interleaved (c0,c1) pairs [48] + c2 [24]
// wdvP  @16396  [124]
// wI    @16520  [248]   interleaved (wcaE, wx) taps
// kI    @16768  [248]   interleaved (keff0*invS0, keff1*invS1) taps
// k2    @17016  [124]   keff2*invS2
// red   @17140  [32]
// scal  @17172  [16]
#define SMEM_FLOATS 17188
#define F2B_STRIDE 324

__device__ __align__(16) float g_K3[1116];
__device__ __align__(16) float g_wcaEff[124];
__device__ float g_speMax;

// ================= precompute kernel (once per launch) =================
__global__ void Spot_pre_kernel(const float* __restrict__ spe,
                                const float* __restrict__ wca,
                                const float* __restrict__ wrl,
                                const float* __restrict__ wsub,
                                const float* __restrict__ wcomb){
  __shared__ float red[32];
  __shared__ float sh[2];
  int tid=threadIdx.x, lane=tid&31, wid=tid>>5;

  float m=-1e30f;
  for(int i=tid;i<1000;i+=TPB) m=fmaxf(m,spe[i]);
#pragma unroll
  for(int o=16;o>0;o>>=1) m=fmaxf(m,__shfl_xor_sync(0xffffffffu,m,o));
  if(lane==0) red[wid]=m;
  __syncthreads();
  if(tid==0){ float mm=red[0]; for(int i=1;i<TPB/32;i++) mm=fmaxf(mm,red[i]);
              sh[0]=mm; g_speMax=mm; }
  __syncthreads();

  float s=0.f;
  for(int i=tid;i<121;i+=TPB) s+=wca[i];
#pragma unroll
  for(int o=16;o>0;o>>=1) s+=__shfl_xor_sync(0xffffffffu,s,o);
  if(lane==0) red[wid]=s;
  __syncthreads();
  if(tid==0){ float ss=0; for(int i=0;i<TPB/32;i++) ss+=red[i]; sh[1]=ss; }
  __syncthreads();
  float swca=sh[1];

  for(int i=tid;i<124;i+=TPB){
    float a =(i<121)? wca[i]:0.f;
    float rl=(i<101)? wrl[i]:0.f;
    g_wcaEff[i]=a - swca*rl;
  }

  // K3[r][c][q] = sum_d sum_k wsub[3d+r][c][k] * wcomb[d][q-k][r]
  for(int e=tid;e<1116;e+=TPB){
    int r=e/372, rem=e-r*372, c=rem/124, q=rem-c*124;
    float acc=0.f;
    if(q<121){
      int klo=(q>100)? (q-100):0;
      int khi=(q<20)? q:20;
      float ad[5]={0,0,0,0,0};
      for(int d=0;d<5;d++){
        const float* ws = wsub + ((3*d+r)*3+c)*21;
        float a2=0.f;
        for(int k=klo;k<=khi;k++)
          a2 = fmaf(ws[k], wcomb[(d*101+(q-k))*3+r], a2);
        ad[d]=a2;
      }
      acc=((ad[0]+ad[1])+(ad[2]+ad[3]))+ad[4];
    }
    g_K3[e]=acc;
  }
}

// ================= packed-math helpers =================
__device__ __forceinline__ ull ffma2(ull a, ull b, ull c){
  ull d;
  asm("fma.rn.f32x2 %0, %1, %2, %3;" : "=l"(d) : "l"(a), "l"(b), "l"(c));
  return d;
}
__device__ __forceinline__ float2 unp(ull a){
  float x,y;
  asm("mov.b64 {%0, %1}, %2;" : "=f"(x), "=f"(y) : "l"(a));
  return make_float2(x,y);
}

// dual-channel conv: 4 outputs x 2 channels. src = interleaved pair array
// (float2 per position), base must point at an EVEN pair position (16B).
// w = interleaved taps. Exact float2 version of the scalar sliding window.
__device__ __forceinline__ void conv4d(const float* __restrict__ src,
                                       const float* __restrict__ w,
                                       int ng, ull* __restrict__ acc){
  const ulonglong2* S = reinterpret_cast<const ulonglong2*>(src);
  const ulonglong2* W = reinterpret_cast<const ulonglong2*>(w);
  ulonglong2 A = S[0];   // pairs p0,p1
  ulonglong2 B = S[1];   // pairs p2,p3
#pragma unroll 2
  for(int g=0; g<ng; g++){
    ulonglong2 C = S[2*g+2];   // p4,p5
    ulonglong2 D = S[2*g+3];   // p6,p7
    ulonglong2 W0 = W[2*g];    // taps 0,1
    ulonglong2 W1 = W[2*g+1];  // taps 2,3
    acc[0]=ffma2(W0.x,A.x,acc[0]); acc[1]=ffma2(W0.x,A.y,acc[1]);
    acc[2]=ffma2(W0.x,B.x,acc[2]); acc[3]=ffma2(W0.x,B.y,acc[3]);
    acc[0]=ffma2(W0.y,A.y,acc[0]); acc[1]=ffma2(W0.y,B.x,acc[1]);
    acc[2]=ffma2(W0.y,B.y,acc[2]); acc[3]=ffma2(W0.y,C.x,acc[3]);
    acc[0]=ffma2(W1.x,B.x,acc[0]); acc[1]=ffma2(W1.x,B.y,acc[1]);
    acc[2]=ffma2(W1.x,C.x,acc[2]); acc[3]=ffma2(W1.x,C.y,acc[3]);
    acc[0]=ffma2(W1.y,B.y,acc[0]); acc[1]=ffma2(W1.y,C.x,acc[1]);
    acc[2]=ffma2(W1.y,C.y,acc[2]); acc[3]=ffma2(W1.y,D.x,acc[3]);
    A=C; B=D;
  }
}

// scalar 4-output sliding-window conv
#define CONV4_BODY(x0,x1,wv,acc)                                               \
  acc[0]=fmaf(wv.x,x0.x,acc[0]); acc[1]=fmaf(wv.x,x0.y,acc[1]);                \
  acc[2]=fmaf(wv.x,x0.z,acc[2]); acc[3]=fmaf(wv.x,x0.w,acc[3]);                \
  acc[0]=fmaf(wv.y,x0.y,acc[0]); acc[1]=fmaf(wv.y,x0.z,acc[1]);                \
  acc[2]=fmaf(wv.y,x0.w,acc[2]); acc[3]=fmaf(wv.y,x1.x,acc[3]);                \
  acc[0]=fmaf(wv.z,x0.z,acc[0]); acc[1]=fmaf(wv.z,x0.w,acc[1]);                \
  acc[2]=fmaf(wv.z,x1.x,acc[2]); acc[3]=fmaf(wv.z,x1.y,acc[3]);                \
  acc[0]=fmaf(wv.w,x0.w,acc[0]); acc[1]=fmaf(wv.w,x1.x,acc[1]);                \
  acc[2]=fmaf(wv.w,x1.y,acc[2]); acc[3]=fmaf(wv.w,x1.z,acc[3]);

template<int NG>
__device__ __forceinline__ void conv4(const float* __restrict__ src,
                                      const float* __restrict__ w,
                                      float* __restrict__ acc){
  float4 x0 = *reinterpret_cast<const float4*>(src);
#pragma unroll
  for(int g=0; g<NG; g++){
    float4 x1 = *reinterpret_cast<const float4*>(src + 4*g + 4);
    float4 wv = *reinterpret_cast<const float4*>(w + 4*g);
    CONV4_BODY(x0,x1,wv,acc)
    x0=x1;
  }
}
__device__ __forceinline__ void conv4r(const float* __restrict__ src,
                                       const float* __restrict__ w,
                                       int ng, float* __restrict__ acc){
  float4 x0 = *reinterpret_cast<const float4*>(src);
#pragma unroll 2
  for(int g=0; g<ng; g++){
    float4 x1 = *reinterpret_cast<const float4*>(src + 4*g + 4);
    float4 wv = *reinterpret_cast<const float4*>(w + 4*g);
    CONV4_BODY(x0,x1,wv,acc)
    x0=x1;
  }
}

// ================= reduction helpers =================
__device__ __forceinline__ float warpRMax(float v){
#pragma unroll
  for(int o=16;o>0;o>>=1) v=fmaxf(v,__shfl_xor_sync(0xffffffffu,v,o));
  return v;
}
__device__ __forceinline__ float warpRSum(float v){
#pragma unroll
  for(int o=16;o>0;o>>=1) v+=__shfl_xor_sync(0xffffffffu,v,o);
  return v;
}
__device__ __forceinline__ void bredMax(float v, float* red, float* out){
  int lane=threadIdx.x&31, wid=threadIdx.x>>5;
  v=warpRMax(v);
  if(lane==0) red[wid]=v;
  __syncthreads();
  if(threadIdx.x==0){
    float m=red[0];
#pragma unroll
    for(int i=1;i<TPB/32;i++) m=fmaxf(m,red[i]);
    *out=m;
  }
  __syncthreads();
}
__device__ __forceinline__ void bredSum(float v, float* red, float* out){
  int lane=threadIdx.x&31, wid=threadIdx.x>>5;
  v=warpRSum(v);
  if(lane==0) red[wid]=v;
  __syncthreads();
  if(threadIdx.x==0){
    float s=red[0];
#pragma unroll
    for(int i=1;i<TPB/32;i++) s+=red[i];
    *out=s;
  }
  __syncthreads();
}

__device__ __forceinline__ float softplusf(float v){
  return (v>0.f) ? v + log1pf(__expf(-v)) : log1pf(__expf(v));
}

// boundary comb half-unit u in [0,260)
__device__ __forceinline__ void do_bnd(int u, const float* __restrict__ f2b,
                                       const float* __restrict__ cwp,
                                       float* __restrict__ part){
  int g26=u/10, q=u%10, p=q>>1, h=q&1;
  int side=g26/13, G=g26%13;
  const float* srcb = f2b + side*160 + 4*G + 52*h;
  const float* wb   = cwp + 52*h;
  float acc[4]={0,0,0,0};
  conv4r(srcb + (3*p  )*F2B_STRIDE, wb+(3*p  )*104, 13, acc);
  conv4r(srcb + (3*p+1)*F2B_STRIDE, wb+(3*p+1)*104, 13, acc);
  conv4r(srcb + (3*p+2)*F2B_STRIDE, wb+(3*p+2)*104, 13, acc);
  float* pp = part + u*4;
  pp[0]=acc[0]; pp[1]=acc[1]; pp[2]=acc[2]; pp[3]=acc[3];
}

// ================= main kernel =================
__global__ void __launch_bounds__(TPB,3) Spot_48610439856277_kernel(
  const float* __restrict__ g_wf, const float* __restrict__ g_mask,
  const float* __restrict__ g_wx, const float* __restrict__ g_wdv,
  const float* __restrict__ g_wsub, const float* __restrict__ g_wcomb,
  const float* __restrict__ g_wp,
  float* __restrict__ g_out)
{
  extern __shared__ float sm[];
  float* wfp  = sm;
  float* cwI  = sm + 1200;
  float* dsp  = sm + 3600;
  float* buf  = sm + 4800;
  float* fnI  = sm + 5824;
  float* fn2  = sm + 7872;
  float* f2b  = sm + 8896;
  float* cwp  = sm + 13756;
  float* wsubI= sm + 15316;
  float* wdvP = sm + 16396;
  float* wI   = sm + 16520;
  float* kI   = sm + 16768;
  float* k2   = sm + 17016;
  float* red  = sm + 17140;
  float* scal = sm + 17172;
  float* part = sm;   // overlays wfp after fit convs
  float2* cwI2=(float2*)cwI;
  float2* fnI2=(float2*)fnI;

  const int tid = threadIdx.x;
  const int lane = tid&31, wid = tid>>5;
  const int b   = blockIdx.x;
  const float* wf = g_wf  + (size_t)b*1000;
  const float* mk = g_mask+ (size_t)b*1000;
  float* outp     = g_out + (size_t)b*1000;

  // ---- preamble loads + pads ----
  for(int i=tid;i<1200;i+=TPB){
    int j=i-100; j = (j<0) ? -j : (j>999 ? 1998-j : j);
    wfp[i]=wf[j];
  }
  for(int i=tid;i<124;i+=TPB){
    float wcaV=g_wcaEff[i];
    float wxV =(i<121)? g_wx[i] :0.f;
    wI[2*i]=wcaV; wI[2*i+1]=wxV;
    wdvP[i]=(i<121)? g_wdv[i]:0.f;
  }
  for(int i=tid;i<1080;i+=TPB){
    int m=i/72, rem=i%72;
    float v;
    if(rem<48){ int k=rem>>1, cin=rem&1; v=(k<21)? g_wsub[(m*3+cin)*21+k]:0.f; }
    else      { int k=rem-48;            v=(k<21)? g_wsub[(m*3+2)*21+k]:0.f; }
    wsubI[i]=v;
  }
  // f2b zero pads: per channel [0,50), [150,160), [260,324)
  for(int i=tid;i<15*124;i+=TPB){
    int c=i/124, j=i%124;
    int off = (j<50)? j : (j<60? 150+(j-50) : 260+(j-60));
    f2b[c*F2B_STRIDE+off]=0.f;
  }
  if(tid<4){ fnI2[1020+tid]=make_float2(0.f,0.f); fn2[1020+tid]=0.f; }
  __syncthreads();

  // ================= Phase A: fused dual scan (cumsum + d1-prefix) + wf max
  {
    int t0=4*tid;
    float la0=0,la1=0,la2=0,la3=0;
    float ld0=0,ld1=0,ld2=0,ld3=0;
    float a0=0,a1=0,a2v=0,a3=0;
    float vmax=-1e30f;
    if(t0<1000){
      a0=wfp[100+t0]; a1=wfp[101+t0]; a2v=wfp[102+t0]; a3=wfp[103+t0];
      la0=a0; la1=la0+a1; la2=la1+a2v; la3=la2+a3;
      vmax=fmaxf(fmaxf(a0,a1),fmaxf(a2v,a3));
      const float dw0=1.f/280.f, dw1=-4.f/105.f, dw2=0.2f, dw3=-0.8f,
                  dw5=0.8f, dw6=-0.2f, dw7=4.f/105.f, dw8=-1.f/280.f;
#pragma unroll
      for(int j=0;j<4;j++){
        int t=t0+j;
        float s=0.f;
        if(t>=4)    s=fmaf(dw0, wfp[ 96+t], s);
        if(t>=3)    s=fmaf(dw1, wfp[ 97+t], s);
        if(t>=2)    s=fmaf(dw2, wfp[ 98+t], s);
        if(t>=1)    s=fmaf(dw3, wfp[ 99+t], s);
        if(t<=998)  s=fmaf(dw5, wfp[101+t], s);
        if(t<=997)  s=fmaf(dw6, wfp[102+t], s);
        if(t<=996)  s=fmaf(dw7, wfp[103+t], s);
        if(t<=995)  s=fmaf(dw8, wfp[104+t], s);
        if(j==0){ ld0=s; } else if(j==1){ ld1=ld0+s; }
        else if(j==2){ ld2=ld1+s; } else { ld3=ld2+s; }
      }
    }
    float csA=la3, xA=csA, csB=ld3, xB=csB;
#pragma unroll
    for(int o=1;o<32;o<<=1){
      float yA=__shfl_up_sync(0xffffffffu,xA,o); if(lane>=o) xA+=yA;
      float yB=__shfl_up_sync(0xffffffffu,xB,o); if(lane>=o) xB+=yB;
    }
    if(lane==31){ red[wid]=xA; red[8+wid]=xB; }
    float wm=warpRMax(vmax);
    if(lane==0) red[16+wid]=wm;
    __syncthreads();
    if(wid==0){
      float z=(lane<8)? red[lane]:0.f;
#pragma unroll
      for(int o=1;o<8;o<<=1){ float y=__shfl_up_sync(0xffffffffu,z,o); if(lane>=o) z+=y; }
      if(lane<8) red[lane]=z;
    } else if(wid==1){
      float z=(lane<8)? red[8+lane]:0.f;
#pragma unroll
      for(int o=1;o<8;o<<=1){ float y=__shfl_up_sync(0xffffffffu,z,o); if(lane>=o) z+=y; }
      if(lane<8) red[8+lane]=z;
    } else if(wid==2 && lane==0){
      float m=red[16];
#pragma unroll
      for(int i=17;i<24;i++) m=fmaxf(m,red[i]);
      scal[0]=m;
    }
    __syncthreads();
    float preA = xA - csA + ((wid>0)? red[wid-1]:0.f);
    float preB = xB - csB + ((wid>0)? red[8+wid-1]:0.f);
    if(t0<1000){
      cwI2[100+t0]=make_float2(preA+la0, a0);
      cwI2[101+t0]=make_float2(preA+la1, a1);
      cwI2[102+t0]=make_float2(preA+la2, a2v);
      cwI2[103+t0]=make_float2(preA+la3, a3);
      buf[t0  ]=preB+ld0; buf[t0+1]=preB+ld1;
      buf[t0+2]=preB+ld2; buf[t0+3]=preB+ld3;
    }
    if(tid==0){  // gate W
      float h = scal[0]/g_speMax;
      float e0=-fmaxf(h-g_wp[0],0.f);
      float e1=-fmaxf(h-g_wp[1],0.f);
      float e2=-fmaxf(h-g_wp[2],0.f);
      float mg=fmaxf(e0,fmaxf(e1,e2));
      float p0=__expf(e0-mg),p1=__expf(e1-mg),p2=__expf(e2-mg);
      float is=1.f/(p0+p1+p2);
      scal[3]=p0*is; scal[4]=p1*is; scal[5]=p2*is;
    }
  }
  __syncthreads();

  // ================= Phase B: cwI halos, dsp from prefixes, cwp build
  for(int i=tid;i<100;i+=TPB){ cwI2[i]=cwI2[200-i]; cwI2[1100+i]=cwI2[1098-i]; }
  for(int t=tid;t<1000;t+=TPB){
    int hi = (t+25>999)? 999 : t+25;
    float p = buf[hi] - ((t>=26)? buf[t-26] : 0.f);
    dsp[100+t]=p*(1.f/51.f);
  }
  for(int i=tid;i<100;i+=TPB){
    int tm=100-i;
    dsp[i] = (buf[tm+25] - ((tm>=26)? buf[tm-26]:0.f))*(1.f/51.f);
    int tr=998-i;
    int hi=(tr+25>999)? 999 : tr+25;
    dsp[1100+i] = (buf[hi] - buf[tr-26])*(1.f/51.f);
  }
  for(int i=tid;i<1560;i+=TPB){
    int c=i/104, hh=i%104, d=c/3, r=c%3;
    cwp[i] = (hh<101) ? scal[3+r]*g_wcomb[(d*101+hh)*3+r] : 0.f;
  }
  __syncthreads();

  // ================= Phase C: fit convs (dual c01 + scalar c2) + inline sums
  float ls0=0.f, ls1=0.f, ls2=0.f;
  if(tid<250){
    int t0=4*tid;
    ull ad[4]={0,0,0,0};
    conv4d(cwI + 2*t0, wI, 31, ad);
    float as[4]={0,0,0,0};
    conv4r(dsp + t0, wdvP, 31, as);
#pragma unroll
    for(int j=0;j<4;j++){
      float2 v=unp(ad[j]);
      float r0=fmaxf(v.x,0.f), r1=fmaxf(v.y,0.f), r2=fmaxf(as[j],0.f);
      fnI2[10+t0+j]=make_float2(r0,r1);
      fn2[10+t0+j]=r2;
      ls0+=r0; ls1+=r1; ls2+=r2;
    }
  }
  {
    float s0=warpRSum(ls0), s1=warpRSum(ls1), s2=warpRSum(ls2);
    if(lane==0){ red[wid]=s0; red[8+wid]=s1; red[16+wid]=s2; }
    __syncthreads();
    if(tid==0){
      float S0=0,S1=0,S2=0;
#pragma unroll
      for(int i=0;i<8;i++){ S0+=red[i]; S1+=red[8+i]; S2+=red[16+i]; }
      scal[6]=1.f/(S0+1e-10f); scal[7]=1.f/(S1+1e-10f); scal[8]=1.f/(S2+1e-10f);
    }
    __syncthreads();
  }

  // ================= Phase D: halos, kI/k2 build (W,invS folded), wsubI*=invS
  for(int i=tid;i<20;i+=TPB){
    if(i<10){ fnI2[i]=fnI2[20-i]; fn2[i]=fn2[20-i]; }
    else { int p=1010+(i-10); fnI2[p]=fnI2[2018-p]; fn2[p]=fn2[2018-p]; }
  }
  for(int i=tid;i<124;i+=TPB){
    float W0=scal[3], W1=scal[4], W2=scal[5];
    float k0=(W0*g_K3[i]     + W1*g_K3[372+i]     + W2*g_K3[744+i]    )*scal[6];
    float k1=(W0*g_K3[124+i] + W1*g_K3[372+124+i] + W2*g_K3[744+124+i])*scal[7];
    float kc2=(W0*g_K3[248+i]+ W1*g_K3[372+248+i] + W2*g_K3[744+248+i])*scal[8];
    ((float2*)kI)[i]=make_float2(k0,k1);
    k2[i]=kc2;
  }
  for(int i=tid;i<1080;i+=TPB){
    int rem=i%72;
    float s = (rem<48)? ((rem&1)? scal[7]:scal[6]) : scal[8];
    wsubI[i]*=s;
  }
  __syncthreads();

  // ================= Phase E: boundary f2 (dual cin01 + scalar cin2)
#pragma unroll 1
  for(int rr=0; rr<3; rr++){
    if(tid<250){
      int u=rr*250+tid;
      int m=u/50, g=u%50;
      int u0 = (g<25)? 4*g : (900+4*(g-25));
      int so = (g<25)? (50+4*g) : (160+4*(g-25));
      ull ad[4]={0,0,0,0};
      float as[4]={0,0,0,0};
      conv4d(fnI + 2*u0, wsubI + m*72, 6, ad);
      conv4<6>(fn2 + u0, wsubI + m*72 + 48, as);
      float* o = f2b + m*F2B_STRIDE + so;
#pragma unroll
      for(int j=0;j<4;j++){
        float2 v=unp(ad[j]);
        o[j]=(v.x+v.y)+as[j];
      }
    }
  }
  __syncthreads();

  // ================= Phase F: interior composite (dual) || boundary comb
  if(tid<225){
    int t0=50+4*tid;
    ull ad[4]={0,0,0,0};
    float as[4]={0,0,0,0};
    conv4d(fnI + 2*(4*tid), kI, 31, ad);
    conv4r(fn2 + 4*tid, k2, 31, as);
#pragma unroll
    for(int j=0;j<4;j++){
      float2 v=unp(ad[j]);
      buf[t0+j]=softplusf((v.x+v.y)+as[j]);
    }
  }
  // boundary: 260 half-units; tid>=225 take 2 each (u 0..61), tid<198 one each
  if(tid>=225){
    do_bnd(tid-225, f2b, cwp, part);
    do_bnd(tid-225+31, f2b, cwp, part);
  } else if(tid<198){
    do_bnd(62+tid, f2b, cwp, part);
  }
  __syncthreads();
  if(tid<104){
    int g26=tid/4, j=tid%4;
    int side=g26/13, G=g26%13;
    int t = side ? (950+4*G+j) : (4*G+j);
    bool valid = side ? (t<1000) : (t<50);
    if(valid){
      float v=0.f;
#pragma unroll
      for(int q=0;q<10;q++) v+=part[(g26*10+q)*4+j];
      buf[t]=softplusf(v);
    }
  }
  __syncthreads();

  // ================= epilogue: amax, masked scale, 1e4-softmax
  {
    float om=-1e30f;
    for(int t=tid;t<1000;t+=TPB) om=fmaxf(om,buf[t]);
    bredMax(om,red,&scal[9]);
    float amax = scal[9] + 1e-10f;

    float ym=-1e30f;
    for(int t=tid;t<1000;t+=TPB){
      float y = 1e4f * ((buf[t]/amax)*mk[t]);
      buf[t]=y; ym=fmaxf(ym,y);
    }
    bredMax(ym,red,&scal[10]);
    float ymax=scal[10];

    float ssum=0.f;
    for(int t=tid;t<1000;t+=TPB){
      float p=__expf(buf[t]-ymax);
      buf[t]=p; ssum+=p;
    }
    bredSum(ssum,red,&scal[11]);
    float isum=1.f/scal[11];
    for(int t=tid;t<1000;t+=TPB) outp[t]=buf[t]*isum;
  }
}

extern "C" void kernel_launch(void* const* d_in, const int* in_sizes, int n_in,
                              void* d_out, int out_size) {
  const float* wf    = (const float*)d_in[0];
  const float* mask  = (const float*)d_in[1];
  const float* SPE   = (const float*)d_in[2];
  const float* wca   = (const float*)d_in[3];
  const float* wx    = (const float*)d_in[4];
  const float* wdv   = (const float*)d_in[5];
  const float* wrl   = (const float*)d_in[6];
  const float* wsub  = (const float*)d_in[7];
  const float* wcomb = (const float*)d_in[8];
  const float* wp    = (const float*)d_in[9];
  float* out = (float*)d_out;

  int B = in_sizes[0] / 1000;
  size_t smem = SMEM_FLOATS * sizeof(float);
  cudaFuncSetAttribute(Spot_48610439856277_kernel,
                       cudaFuncAttributeMaxDynamicSharedMemorySize, (int)smem);

  Spot_pre_kernel<<<1, TPB>>>(SPE, wca, wrl, wsub, wcomb);
  Spot_48610439856277_kernel<<<B, TPB, smem>>>(wf, mask, wx, wdv,
                                               wsub, wcomb, wp, out);
}

// round 14
// speedup vs baseline: 1.2489x; 1.2452x over previous
#include <cuda_runtime.h>
#include <math.h>

#define TPB 256

// ---------------- shared-memory layout (floats) ----------------
// wfp   @0      [1200]  reflect-padded waveform
// cp    @1200   [1200]  reflect-padded cumsum
// dsp   @2400   [1200]  reflect-padded smoothed deriv
// buf   @3600   [1024]  d1-prefix / comp / final
// fnp   @4624   [3456]  3 slabs x 1152: zeros[0,54) | reflect10 | fn@64 | reflect10 | zeros
// f2v   @8080   [1560]  15 ch x (52 left | 52 right) virtual f2
// cwp   @9640   [1560]  W-folded comb weights 15 x 104
// wsubp @11200  [1080]  15 x 3 x 24 (invS folded before use)
// wcaE  @12280  [124]
// wxP   @12404  [124]
// wdvP  @12528  [124]
// keff  @12652  [372]   composite kernel 3 x 124 (W and invS folded)
// red   @13024  [32]
// scal  @13056  [16]
#define SMEM_FLOATS 13072
#define SLAB 1152

__device__ __align__(16) float g_K3[1116];
__device__ __align__(16) float g_wcaEff[124];
__device__ float g_speMax;

// ================= precompute kernel (once per launch) =================
__global__ void Spot_pre_kernel(const float* __restrict__ spe,
                                const float* __restrict__ wca,
                                const float* __restrict__ wrl,
                                const float* __restrict__ wsub,
                                const float* __restrict__ wcomb){
  __shared__ float red[32];
  __shared__ float sh[2];
  int tid=threadIdx.x, lane=tid&31, wid=tid>>5;

  float m=-1e30f;
  for(int i=tid;i<1000;i+=TPB) m=fmaxf(m,spe[i]);
#pragma unroll
  for(int o=16;o>0;o>>=1) m=fmaxf(m,__shfl_xor_sync(0xffffffffu,m,o));
  if(lane==0) red[wid]=m;
  __syncthreads();
  if(tid==0){ float mm=red[0]; for(int i=1;i<TPB/32;i++) mm=fmaxf(mm,red[i]);
              sh[0]=mm; g_speMax=mm; }
  __syncthreads();

  float s=0.f;
  for(int i=tid;i<121;i+=TPB) s+=wca[i];
#pragma unroll
  for(int o=16;o>0;o>>=1) s+=__shfl_xor_sync(0xffffffffu,s,o);
  if(lane==0) red[wid]=s;
  __syncthreads();
  if(tid==0){ float ss=0; for(int i=0;i<TPB/32;i++) ss+=red[i]; sh[1]=ss; }
  __syncthreads();
  float swca=sh[1];

  for(int i=tid;i<124;i+=TPB){
    float a =(i<121)? wca[i]:0.f;
    float rl=(i<101)? wrl[i]:0.f;
    g_wcaEff[i]=a - swca*rl;
  }

  // K3[r][c][q] = sum_d sum_k wsub[3d+r][c][k] * wcomb[d][q-k][r]
  for(int e=tid;e<1116;e+=TPB){
    int r=e/372, rem=e-r*372, c=rem/124, q=rem-c*124;
    float acc=0.f;
    if(q<121){
      int klo=(q>100)? (q-100):0;
      int khi=(q<20)? q:20;
      float ad[5]={0,0,0,0,0};
      for(int d=0;d<5;d++){
        const float* ws = wsub + ((3*d+r)*3+c)*21;
        float a2=0.f;
        for(int k=klo;k<=khi;k++)
          a2 = fmaf(ws[k], wcomb[(d*101+(q-k))*3+r], a2);
        ad[d]=a2;
      }
      acc=((ad[0]+ad[1])+(ad[2]+ad[3]))+ad[4];
    }
    g_K3[e]=acc;
  }
}

// ================= conv helpers (R6-proven) =================
#define CONV4_BODY(x0,x1,wv,acc)                                               \
  acc[0]=fmaf(wv.x,x0.x,acc[0]); acc[1]=fmaf(wv.x,x0.y,acc[1]);                \
  acc[2]=fmaf(wv.x,x0.z,acc[2]); acc[3]=fmaf(wv.x,x0.w,acc[3]);                \
  acc[0]=fmaf(wv.y,x0.y,acc[0]); acc[1]=fmaf(wv.y,x0.z,acc[1]);                \
  acc[2]=fmaf(wv.y,x0.w,acc[2]); acc[3]=fmaf(wv.y,x1.x,acc[3]);                \
  acc[0]=fmaf(wv.z,x0.z,acc[0]); acc[1]=fmaf(wv.z,x0.w,acc[1]);                \
  acc[2]=fmaf(wv.z,x1.x,acc[2]); acc[3]=fmaf(wv.z,x1.y,acc[3]);                \
  acc[0]=fmaf(wv.w,x0.w,acc[0]); acc[1]=fmaf(wv.w,x1.x,acc[1]);                \
  acc[2]=fmaf(wv.w,x1.y,acc[2]); acc[3]=fmaf(wv.w,x1.z,acc[3]);

template<int NG>
__device__ __forceinline__ void conv4(const float* __restrict__ src,
                                      const float* __restrict__ w,
                                      float* __restrict__ acc){
  float4 x0 = *reinterpret_cast<const float4*>(src);
#pragma unroll
  for(int g=0; g<NG; g++){
    float4 x1 = *reinterpret_cast<const float4*>(src + 4*g + 4);
    float4 wv = *reinterpret_cast<const float4*>(w + 4*g);
    CONV4_BODY(x0,x1,wv,acc)
    x0=x1;
  }
}
__device__ __forceinline__ void conv4r(const float* __restrict__ src,
                                       const float* __restrict__ w,
                                       int ng, float* __restrict__ acc){
  float4 x0 = *reinterpret_cast<const float4*>(src);
#pragma unroll 2
  for(int g=0; g<ng; g++){
    float4 x1 = *reinterpret_cast<const float4*>(src + 4*g + 4);
    float4 wv = *reinterpret_cast<const float4*>(w + 4*g);
    CONV4_BODY(x0,x1,wv,acc)
    x0=x1;
  }
}

// ================= reduction helpers =================
__device__ __forceinline__ float warpRMax(float v){
#pragma unroll
  for(int o=16;o>0;o>>=1) v=fmaxf(v,__shfl_xor_sync(0xffffffffu,v,o));
  return v;
}
__device__ __forceinline__ float warpRSum(float v){
#pragma unroll
  for(int o=16;o>0;o>>=1) v+=__shfl_xor_sync(0xffffffffu,v,o);
  return v;
}
__device__ __forceinline__ void bredMax(float v, float* red, float* out){
  int lane=threadIdx.x&31, wid=threadIdx.x>>5;
  v=warpRMax(v);
  if(lane==0) red[wid]=v;
  __syncthreads();
  if(threadIdx.x==0){
    float m=red[0];
#pragma unroll
    for(int i=1;i<TPB/32;i++) m=fmaxf(m,red[i]);
    *out=m;
  }
  __syncthreads();
}
__device__ __forceinline__ void bredSum(float v, float* red, float* out){
  int lane=threadIdx.x&31, wid=threadIdx.x>>5;
  v=warpRSum(v);
  if(lane==0) red[wid]=v;
  __syncthreads();
  if(threadIdx.x==0){
    float s=red[0];
#pragma unroll
    for(int i=1;i<TPB/32;i++) s+=red[i];
    *out=s;
  }
  __syncthreads();
}

__device__ __forceinline__ float softplusf(float v){
  return (v>0.f) ? v + log1pf(__expf(-v)) : log1pf(__expf(v));
}

// virtual f2 unit u in [0,390): m=u/26, side, group j. 4 outputs.
__device__ __forceinline__ void f2v_unit(int u, const float* __restrict__ fnp,
                                         const float* __restrict__ wsubp,
                                         float* __restrict__ f2v){
  int m=u/26, r26=u-26*m, side=r26/13, j=r26-13*side;
  int soff = side? (1052+4*j) : (4+4*j);
  float acc[4]={0,0,0,0};
  const float* wm = wsubp + m*72;
  conv4<6>(fnp          + soff, wm   , acc);
  conv4<6>(fnp +   SLAB + soff, wm+24, acc);
  conv4<6>(fnp + 2*SLAB + soff, wm+48, acc);
  float* o = f2v + m*104 + side*52 + 4*j;
  o[0]=acc[0]; o[1]=acc[1]; o[2]=acc[2]; o[3]=acc[3];
}

// ================= main kernel =================
__global__ void __launch_bounds__(TPB,3) Spot_48610439856277_kernel(
  const float* __restrict__ g_wf, const float* __restrict__ g_mask,
  const float* __restrict__ g_wx, const float* __restrict__ g_wdv,
  const float* __restrict__ g_wsub, const float* __restrict__ g_wcomb,
  const float* __restrict__ g_wp,
  float* __restrict__ g_out)
{
  extern __shared__ float sm[];
  float* wfp  = sm;
  float* cp   = sm + 1200;
  float* dsp  = sm + 2400;
  float* buf  = sm + 3600;
  float* fnp  = sm + 4624;
  float* f2v  = sm + 8080;
  float* cwp  = sm + 9640;
  float* wsubp= sm + 11200;
  float* wcaE = sm + 12280;
  float* wxP  = sm + 12404;
  float* wdvP = sm + 12528;
  float* keff = sm + 12652;
  float* red  = sm + 13024;
  float* scal = sm + 13056;

  const int tid = threadIdx.x;
  const int lane = tid&31, wid = tid>>5;
  const int b   = blockIdx.x;
  const float* wf = g_wf  + (size_t)b*1000;
  const float* mk = g_mask+ (size_t)b*1000;
  float* outp     = g_out + (size_t)b*1000;

  // ---- preamble loads + pads ----
  for(int i=tid;i<1200;i+=TPB){
    int j=i-100; j = (j<0) ? -j : (j>999 ? 1998-j : j);
    wfp[i]=wf[j];
  }
  for(int i=tid;i<124;i+=TPB){
    wcaE[i]=g_wcaEff[i];
    wxP[i] =(i<121)? g_wx[i] :0.f;
    wdvP[i]=(i<121)? g_wdv[i]:0.f;
  }
  for(int i=tid;i<1080;i+=TPB){
    int m=i/72, rem=i%72, cin=rem/24, k=rem%24;
    wsubp[i] = (k<21)? g_wsub[(m*3+cin)*21+k] : 0.f;
  }
  // fnp slab zero pads: [0,54) and [1074,1132) per slab
  for(int i=tid;i<3*112;i+=TPB){
    int c=i/112, j=i%112;
    int off = (j<54)? j : (1074 + (j-54));
    fnp[c*SLAB+off]=0.f;
  }
  __syncthreads();

  // ================= Phase A: fused dual scan (cumsum + d1-prefix) + wf max
  {
    int t0=4*tid;
    float la0=0,la1=0,la2=0,la3=0;
    float ld0=0,ld1=0,ld2=0,ld3=0;
    float vmax=-1e30f;
    if(t0<1000){
      float a0=wfp[100+t0], a1=wfp[101+t0], a2=wfp[102+t0], a3=wfp[103+t0];
      la0=a0; la1=la0+a1; la2=la1+a2; la3=la2+a3;
      vmax=fmaxf(fmaxf(a0,a1),fmaxf(a2,a3));
      const float dw0=1.f/280.f, dw1=-4.f/105.f, dw2=0.2f, dw3=-0.8f,
                  dw5=0.8f, dw6=-0.2f, dw7=4.f/105.f, dw8=-1.f/280.f;
#pragma unroll
      for(int j=0;j<4;j++){
        int t=t0+j;
        float s=0.f;
        if(t>=4)    s=fmaf(dw0, wfp[ 96+t], s);
        if(t>=3)    s=fmaf(dw1, wfp[ 97+t], s);
        if(t>=2)    s=fmaf(dw2, wfp[ 98+t], s);
        if(t>=1)    s=fmaf(dw3, wfp[ 99+t], s);
        if(t<=998)  s=fmaf(dw5, wfp[101+t], s);
        if(t<=997)  s=fmaf(dw6, wfp[102+t], s);
        if(t<=996)  s=fmaf(dw7, wfp[103+t], s);
        if(t<=995)  s=fmaf(dw8, wfp[104+t], s);
        if(j==0){ ld0=s; } else if(j==1){ ld1=ld0+s; }
        else if(j==2){ ld2=ld1+s; } else { ld3=ld2+s; }
      }
    }
    float csA=la3, xA=csA, csB=ld3, xB=csB;
#pragma unroll
    for(int o=1;o<32;o<<=1){
      float yA=__shfl_up_sync(0xffffffffu,xA,o); if(lane>=o) xA+=yA;
      float yB=__shfl_up_sync(0xffffffffu,xB,o); if(lane>=o) xB+=yB;
    }
    if(lane==31){ red[wid]=xA; red[8+wid]=xB; }
    float wm=warpRMax(vmax);
    if(lane==0) red[16+wid]=wm;
    __syncthreads();
    if(wid==0){
      float z=(lane<8)? red[lane]:0.f;
#pragma unroll
      for(int o=1;o<8;o<<=1){ float y=__shfl_up_sync(0xffffffffu,z,o); if(lane>=o) z+=y; }
      if(lane<8) red[lane]=z;
    } else if(wid==1){
      float z=(lane<8)? red[8+lane]:0.f;
#pragma unroll
      for(int o=1;o<8;o<<=1){ float y=__shfl_up_sync(0xffffffffu,z,o); if(lane>=o) z+=y; }
      if(lane<8) red[8+lane]=z;
    } else if(wid==2 && lane==0){
      float m=red[16];
#pragma unroll
      for(int i=17;i<24;i++) m=fmaxf(m,red[i]);
      scal[0]=m;
    }
    __syncthreads();
    float preA = xA - csA + ((wid>0)? red[wid-1]:0.f);
    float preB = xB - csB + ((wid>0)? red[8+wid-1]:0.f);
    if(t0<1000){
      cp[100+t0]=preA+la0; cp[101+t0]=preA+la1;
      cp[102+t0]=preA+la2; cp[103+t0]=preA+la3;
      buf[t0  ]=preB+ld0; buf[t0+1]=preB+ld1;
      buf[t0+2]=preB+ld2; buf[t0+3]=preB+ld3;
    }
    if(tid==0){
      float h = scal[0]/g_speMax;
      float e0=-fmaxf(h-g_wp[0],0.f);
      float e1=-fmaxf(h-g_wp[1],0.f);
      float e2=-fmaxf(h-g_wp[2],0.f);
      float mg=fmaxf(e0,fmaxf(e1,e2));
      float p0=__expf(e0-mg),p1=__expf(e1-mg),p2=__expf(e2-mg);
      float is=1.f/(p0+p1+p2);
      scal[3]=p0*is; scal[4]=p1*is; scal[5]=p2*is;
    }
  }
  __syncthreads();

  // ================= Phase B: cp halos, dsp from prefixes, cwp build
  for(int i=tid;i<100;i+=TPB){ cp[i]=cp[200-i]; cp[1100+i]=cp[1098-i]; }
  for(int t=tid;t<1000;t+=TPB){
    int hi = (t+25>999)? 999 : t+25;
    float p = buf[hi] - ((t>=26)? buf[t-26] : 0.f);
    dsp[100+t]=p*(1.f/51.f);
  }
  for(int i=tid;i<100;i+=TPB){
    int tm=100-i;
    dsp[i] = (buf[tm+25] - ((tm>=26)? buf[tm-26]:0.f))*(1.f/51.f);
    int tr=998-i;
    int hi=(tr+25>999)? 999 : tr+25;
    dsp[1100+i] = (buf[hi] - buf[tr-26])*(1.f/51.f);
  }
  for(int i=tid;i<1560;i+=TPB){
    int c=i/104, hh=i%104, d=c/3, r=c%3;
    cwp[i] = (hh<101) ? scal[3+r]*g_wcomb[(d*101+hh)*3+r] : 0.f;
  }
  __syncthreads();

  // ================= Phase C: fit convs (raw relu -> slabs) + inline sums
  float ls0=0.f, ls1=0.f, ls2=0.f;
  if(tid<250){
    int t0=4*tid;
    {
      float a[4]={0,0,0,0};
      conv4r(cp +t0, wcaE, 31, a);
#pragma unroll
      for(int j=0;j<4;j++){ float r=fmaxf(a[j],0.f); fnp[64+t0+j]=r; ls0+=r; }
    }
    {
      float a[4]={0,0,0,0};
      conv4r(wfp+t0, wxP , 31, a);
#pragma unroll
      for(int j=0;j<4;j++){ float r=fmaxf(a[j],0.f); fnp[SLAB+64+t0+j]=r; ls1+=r; }
    }
    {
      float a[4]={0,0,0,0};
      conv4r(dsp+t0, wdvP, 31, a);
#pragma unroll
      for(int j=0;j<4;j++){ float r=fmaxf(a[j],0.f); fnp[2*SLAB+64+t0+j]=r; ls2+=r; }
    }
  }
  {
    float s0=warpRSum(ls0), s1=warpRSum(ls1), s2=warpRSum(ls2);
    if(lane==0){ red[wid]=s0; red[8+wid]=s1; red[16+wid]=s2; }
    __syncthreads();
    if(tid==0){
      float S0=0,S1=0,S2=0;
#pragma unroll
      for(int i=0;i<8;i++){ S0+=red[i]; S1+=red[8+i]; S2+=red[16+i]; }
      scal[6]=1.f/(S0+1e-10f); scal[7]=1.f/(S1+1e-10f); scal[8]=1.f/(S2+1e-10f);
    }
    __syncthreads();
  }

  // ================= Phase D: slab reflect halos, keff build, wsubp*=invS
  for(int i=tid;i<60;i+=TPB){
    int c=i/20, q=i%20;
    float* f=fnp+c*SLAB;
    if(q<10) f[63-q]=f[65+q];              // j=q+1: [64-j]=[64+j]
    else { int j=q-10; f[1064+j]=f[1062-j]; }
  }
  for(int i=tid;i<372;i+=TPB){
    int c=i/124;
    keff[i] = (scal[3]*g_K3[i] + scal[4]*g_K3[372+i] + scal[5]*g_K3[744+i])*scal[6+c];
  }
  for(int i=tid;i<1080;i+=TPB){
    int c=(i%72)/24;
    wsubp[i]*=scal[6+c];
  }
  __syncthreads();

  // ================= Phase EF: full composite (250 thr) + virtual f2 (390 units)
  if(tid<250){
    int t0=4*tid;
    float acc[4]={0,0,0,0};
    conv4r(fnp          + t0 + 4, keff    , 31, acc);
    conv4r(fnp +   SLAB + t0 + 4, keff+124, 31, acc);
    conv4r(fnp + 2*SLAB + t0 + 4, keff+248, 31, acc);
#pragma unroll
    for(int j=0;j<4;j++){
      int t=t0+j;
      buf[t] = (t>=50 && t<950) ? softplusf(acc[j]) : acc[j];
    }
    f2v_unit(30+tid, fnp, wsubp, f2v);
    if(tid<110) f2v_unit(280+tid, fnp, wsubp, f2v);
  } else {
#pragma unroll 1
    for(int q=0;q<5;q++) f2v_unit((tid-250)+6*q, fnp, wsubp, f2v);
  }
  __syncthreads();

  // ================= Phase G: boundary corrections + softplus
  if(tid<100){
    float corr=0.f;
    int t;
    if(tid<50){
      t=tid;
      int n=50-t;
#pragma unroll 1
      for(int c=0;c<15;c++){
        const float* cw=cwp+c*104;
        const float* fv=f2v+c*104+t;
        float s=0.f;
        for(int h=0;h<n;h++) s=fmaf(cw[h],fv[h],s);
        corr+=s;
      }
    } else {
      t=900+tid;   // 950..999
      int n=t-949, h0=1050-t;
#pragma unroll 1
      for(int c=0;c<15;c++){
        const float* cw=cwp+c*104+h0;
        const float* fv=f2v+c*104+54;
        float s=0.f;
        for(int i=0;i<n;i++) s=fmaf(cw[i],fv[i],s);
        corr+=s;
      }
    }
    buf[t]=softplusf(buf[t]-corr);
  }
  __syncthreads();

  // ================= epilogue: amax, masked scale, 1e4-softmax
  {
    float om=-1e30f;
    for(int t=tid;t<1000;t+=TPB) om=fmaxf(om,buf[t]);
    bredMax(om,red,&scal[9]);
    float amax = scal[9] + 1e-10f;

    float ym=-1e30f;
    for(int t=tid;t<1000;t+=TPB){
      float y = 1e4f * ((buf[t]/amax)*mk[t]);
      buf[t]=y; ym=fmaxf(ym,y);
    }
    bredMax(ym,red,&scal[10]);
    float ymax=scal[10];

    float ssum=0.f;
    for(int t=tid;t<1000;t+=TPB){
      float p=__expf(buf[t]-ymax);
      buf[t]=p; ssum+=p;
    }
    bredSum(ssum,red,&scal[11]);
    float isum=1.f/scal[11];
    for(int t=tid;t<1000;t+=TPB) outp[t]=buf[t]*isum;
  }
}

extern "C" void kernel_launch(void* const* d_in, const int* in_sizes, int n_in,
                              void* d_out, int out_size) {
  const float* wf    = (const float*)d_in[0];
  const float* mask  = (const float*)d_in[1];
  const float* SPE   = (const float*)d_in[2];
  const float* wca   = (const float*)d_in[3];
  const float* wx    = (const float*)d_in[4];
  const float* wdv   = (const float*)d_in[5];
  const float* wrl   = (const float*)d_in[6];
  const float* wsub  = (const float*)d_in[7];
  const float* wcomb = (const float*)d_in[8];
  const float* wp    = (const float*)d_in[9];
  float* out = (float*)d_out;

  int B = in_sizes[0] / 1000;
  size_t smem = SMEM_FLOATS * sizeof(float);
  cudaFuncSetAttribute(Spot_48610439856277_kernel,
                       cudaFuncAttributeMaxDynamicSharedMemorySize, (int)smem);

  Spot_pre_kernel<<<1, TPB>>>(SPE, wca, wrl, wsub, wcomb);
  Spot_48610439856277_kernel<<<B, TPB, smem>>>(wf, mask, wx, wdv,
                                               wsub, wcomb, wp, out);
}